// round 1
// baseline (speedup 1.0000x reference)
#include <cuda_runtime.h>
#include <cuda_bf16.h>

#define Cdim 128
#define Hdim 320
#define Wdim 320
#define TW 20
#define TH 5
#define Ppix 100     // valid pixels per tile
#define PITCH 105    // padded pitch (odd => 4-way instead of 32-way conflicts)

// ---- precomputed folded weights (device globals; no allocation) ----
__device__ float g_WchT[128 * 128];   // [i][o] : W_fuse[:, :128] @ Wh_pw, transposed
__device__ float g_WcvT[128 * 128];   // [i][o] : W_fuse[:, 128:] @ Wv_pw, transposed
__device__ float g_dm1T[128 * 32];    // [o][m]
__device__ float g_dm2T[32 * 128];    // [m][o]

__global__ void precompute_kernel(const float* __restrict__ w_h_pw,
                                  const float* __restrict__ w_v_pw,
                                  const float* __restrict__ w_dm1,
                                  const float* __restrict__ w_dm2,
                                  const float* __restrict__ w_fuse) {
    int o = blockIdx.x;
    int t = threadIdx.x;   // 128 threads
    if (o < 128) {
        float s1 = 0.f, s2 = 0.f;
        #pragma unroll 4
        for (int j = 0; j < 128; ++j) {
            s1 += w_fuse[o * 256 + j]       * w_h_pw[j * 128 + t];
            s2 += w_fuse[o * 256 + 128 + j] * w_v_pw[j * 128 + t];
        }
        g_WchT[t * 128 + o] = s1;
        g_WcvT[t * 128 + o] = s2;
    } else if (o == 128) {
        for (int idx = t; idx < 32 * 128; idx += 128) {
            int oo = idx / 32, m = idx % 32;
            g_dm1T[oo * 32 + m] = w_dm1[m * 128 + oo];
        }
    } else {
        for (int idx = t; idx < 32 * 128; idx += 128) {
            int m = idx / 128, oo = idx % 128;
            g_dm2T[m * 128 + oo] = w_dm2[oo * 32 + m];
        }
    }
}

// ---- shared memory layout (floats) ----
// ash  [0      , 13440)  : a_h [128][PITCH]        (dbuf aliases this in phase 5/6)
// asv  [13440  , 26880)  : a_v [128][PITCH]
// epi  [26880  , 40320)  : epi [128][PITCH]        (sx aliases this in phase 1/2)
// wbuf [40320  , 44416)  : 32x128 weight chunk
// st   [44416  , 47776)  : t  [32][PITCH]
// dwg  [47776  , 49056)  : depthwise weights [2][128][5]
#define SM_FLOATS 49056

__global__ __launch_bounds__(256, 1)
void epi_fused_kernel(const float* __restrict__ x,
                      const float* __restrict__ w_h_dw,
                      const float* __restrict__ w_v_dw,
                      const float* __restrict__ scale_p,
                      float* __restrict__ out) {
    extern __shared__ float sm[];
    float* ash  = sm;
    float* asv  = sm + 13440;
    float* epi  = sm + 26880;
    float* sx   = epi;            // x tile [128][100], alias (freed before epi written)
    float* wbuf = sm + 40320;
    float* st   = sm + 44416;
    float* dwg  = sm + 47776;
    float* dbuf = sm;             // d [128][PITCH], aliases ash (freed after GEMM)

    const int tid = threadIdx.x;
    const int C0 = blockIdx.x * TW;
    const int R0 = blockIdx.y * TH;
    const int b  = blockIdx.z;

    const float* xb = x + (long)b * Cdim * (Hdim * Wdim);

    // ---- P1: stage x tile (float4, coalesced) + depthwise weights ----
    for (int idx = tid; idx < 640 * 5; idx += 256) {
        int row = idx / 5;            // c*5 + r
        int q   = idx % 5;
        int c = row / 5, r = row % 5;
        float4 v = *reinterpret_cast<const float4*>(
            xb + (long)c * (Hdim * Wdim) + (R0 + r) * Wdim + C0 + q * 4);
        *reinterpret_cast<float4*>(sx + c * 100 + r * 20 + q * 4) = v;
    }
    for (int idx = tid; idx < 640; idx += 256) {
        dwg[idx]       = w_h_dw[idx];   // (C,1,1,5) contiguous
        dwg[640 + idx] = w_v_dw[idx];   // (C,1,5,1) contiguous
    }
    __syncthreads();

    // ---- P2: depthwise 1x5 / 5x1 within angular block + leaky relu ----
    for (int idx = tid; idx < Cdim * Ppix; idx += 256) {
        int c = idx / Ppix;
        int p = idx % Ppix;
        int r = p / TW, col = p % TW;
        int v = col % 5;              // angular column within block
        const float* rowp = sx + c * 100 + r * 20;
        const float* wh = dwg + c * 5;
        const float* wv = dwg + 640 + c * 5;
        float hs = 0.f, vs = 0.f;
        #pragma unroll
        for (int k = 0; k < 5; ++k) {
            int d = k - 2;
            if (v + d >= 0 && v + d < 5) hs += wh[k] * rowp[col + d];
            if (r + d >= 0 && r + d < 5) vs += wv[k] * sx[c * 100 + (r + d) * 20 + col];
        }
        ash[c * PITCH + p] = hs > 0.f ? hs : 0.1f * hs;
        asv[c * PITCH + p] = vs > 0.f ? vs : 0.1f * vs;
    }
    for (int idx = tid; idx < Cdim * (PITCH - Ppix); idx += 256) {
        int c = idx / (PITCH - Ppix), p = Ppix + idx % (PITCH - Ppix);
        ash[c * PITCH + p] = 0.f;
        asv[c * PITCH + p] = 0.f;
    }

    // ---- P3: epi = WchT^T @ a_h + WcvT^T @ a_v  (128o x 104p x 256K) ----
    const int lane = tid & 31;
    const int wg   = tid >> 5;
    const int o0 = lane * 4;
    const int p0 = wg * 13;
    float acc[4][13];
    #pragma unroll
    for (int a = 0; a < 4; ++a)
        #pragma unroll
        for (int j = 0; j < 13; ++j) acc[a][j] = 0.f;

    for (int s = 0; s < 2; ++s) {
        const float* A  = s ? asv : ash;
        const float* gW = s ? g_WcvT : g_WchT;
        for (int ch = 0; ch < 4; ++ch) {
            __syncthreads();   // wbuf free / (first time) P2 done
            for (int idx = tid; idx < 1024; idx += 256)
                reinterpret_cast<float4*>(wbuf)[idx] =
                    reinterpret_cast<const float4*>(gW + ch * 4096)[idx];
            __syncthreads();
            const float* Ab = A + ch * 32 * PITCH;
            #pragma unroll 2
            for (int ii = 0; ii < 32; ++ii) {
                float4 w = *reinterpret_cast<const float4*>(wbuf + ii * 128 + o0);
                const float* ap = Ab + ii * PITCH + p0;   // broadcast across lanes
                float av[13];
                #pragma unroll
                for (int j = 0; j < 13; ++j) av[j] = ap[j];
                #pragma unroll
                for (int j = 0; j < 13; ++j) {
                    acc[0][j] += w.x * av[j];
                    acc[1][j] += w.y * av[j];
                    acc[2][j] += w.z * av[j];
                    acc[3][j] += w.w * av[j];
                }
            }
        }
    }
    #pragma unroll
    for (int a = 0; a < 4; ++a) {
        float* ep = epi + (o0 + a) * PITCH + p0;
        #pragma unroll
        for (int j = 0; j < 13; ++j) ep[j] = acc[a][j];
    }
    __syncthreads();   // epi visible, wbuf free

    // ---- P4: t = lrelu(dm1 @ epi)  (32 x 104, K=128) ----
    for (int idx = tid; idx < 1024; idx += 256)
        reinterpret_cast<float4*>(wbuf)[idx] =
            reinterpret_cast<const float4*>(g_dm1T)[idx];
    __syncthreads();
    {
        float a2[13];
        #pragma unroll
        for (int j = 0; j < 13; ++j) a2[j] = 0.f;
        const int m = lane;
        #pragma unroll 4
        for (int o = 0; o < 128; ++o) {
            float wv = wbuf[o * 32 + m];
            const float* ep = epi + o * PITCH + p0;
            #pragma unroll
            for (int j = 0; j < 13; ++j) a2[j] += wv * ep[j];
        }
        float* tp = st + m * PITCH + p0;
        #pragma unroll
        for (int j = 0; j < 13; ++j) { float v = a2[j]; tp[j] = v > 0.f ? v : 0.1f * v; }
    }
    __syncthreads();

    // ---- P5: d = sigmoid(dm2 @ t)  (128 x 104, K=32) ----
    for (int idx = tid; idx < 1024; idx += 256)
        reinterpret_cast<float4*>(wbuf)[idx] =
            reinterpret_cast<const float4*>(g_dm2T)[idx];
    __syncthreads();
    {
        float a3[4][13];
        #pragma unroll
        for (int a = 0; a < 4; ++a)
            #pragma unroll
            for (int j = 0; j < 13; ++j) a3[a][j] = 0.f;
        #pragma unroll 4
        for (int m = 0; m < 32; ++m) {
            float4 w = *reinterpret_cast<const float4*>(wbuf + m * 128 + o0);
            const float* tp = st + m * PITCH + p0;   // broadcast
            #pragma unroll
            for (int j = 0; j < 13; ++j) {
                float tv = tp[j];
                a3[0][j] += w.x * tv;
                a3[1][j] += w.y * tv;
                a3[2][j] += w.z * tv;
                a3[3][j] += w.w * tv;
            }
        }
        #pragma unroll
        for (int a = 0; a < 4; ++a) {
            float* dp = dbuf + (o0 + a) * PITCH + p0;
            #pragma unroll
            for (int j = 0; j < 13; ++j)
                dp[j] = 1.f / (1.f + __expf(-a3[a][j]));
        }
    }
    __syncthreads();

    // ---- P6: out = x + scale * epi * d  (coalesced) ----
    const float s = scale_p[0];
    float* ob = out + (long)b * Cdim * (Hdim * Wdim);
    for (int idx = tid; idx < Cdim * Ppix; idx += 256) {
        int c = idx / Ppix, p = idx % Ppix;
        int r = p / TW, col = p % TW;
        long g = (long)c * (Hdim * Wdim) + (long)(R0 + r) * Wdim + C0 + col;
        ob[g] = xb[g] + s * epi[c * PITCH + p] * dbuf[c * PITCH + p];
    }
}

extern "C" void kernel_launch(void* const* d_in, const int* in_sizes, int n_in,
                              void* d_out, int out_size) {
    const float* x       = (const float*)d_in[0];
    const float* w_h_dw  = (const float*)d_in[1];
    const float* w_h_pw  = (const float*)d_in[2];
    const float* w_v_dw  = (const float*)d_in[3];
    const float* w_v_pw  = (const float*)d_in[4];
    const float* w_dm1   = (const float*)d_in[5];
    const float* w_dm2   = (const float*)d_in[6];
    const float* w_fuse  = (const float*)d_in[7];
    const float* scale   = (const float*)d_in[8];

    precompute_kernel<<<130, 128>>>(w_h_pw, w_v_pw, w_dm1, w_dm2, w_fuse);

    cudaFuncSetAttribute(epi_fused_kernel,
                         cudaFuncAttributeMaxDynamicSharedMemorySize,
                         SM_FLOATS * sizeof(float));
    dim3 grid(Wdim / TW, Hdim / TH, 2);
    epi_fused_kernel<<<grid, 256, SM_FLOATS * sizeof(float)>>>(
        x, w_h_dw, w_v_dw, scale, (float*)d_out);
}

// round 2
// speedup vs baseline: 1.9395x; 1.9395x over previous
#include <cuda_runtime.h>
#include <cuda_bf16.h>

#define Cdim   128
#define HW     102400          // 320*320
#define APITCH 120             // act/epi/t/d pitch (elems): 240B rows -> conflict-free ldmatrix.trans
#define WMP    264             // Wmain smem pitch (528B rows)
#define W1P    136             // Wdm1 smem pitch (272B rows)
#define W2P    40              // Wdm2 smem pitch (80B rows)

// ---- precomputed folded weights (bf16, device globals) ----
__device__ __align__(16) __nv_bfloat16 g_Wmain[128 * 256]; // [o][k]: k<128 -> Wch, k>=128 -> Wcv
__device__ __align__(16) __nv_bfloat16 g_Wdm1[32 * 128];   // [m][o]
__device__ __align__(16) __nv_bfloat16 g_Wdm2[128 * 32];   // [o][m]

__global__ void precompute_kernel(const float* __restrict__ w_h_pw,
                                  const float* __restrict__ w_v_pw,
                                  const float* __restrict__ w_dm1,
                                  const float* __restrict__ w_dm2,
                                  const float* __restrict__ w_fuse) {
    int o = blockIdx.x;
    int t = threadIdx.x;   // 128 threads
    if (o < 128) {
        float s1 = 0.f, s2 = 0.f;
        #pragma unroll 4
        for (int j = 0; j < 128; ++j) {
            s1 += w_fuse[o * 256 + j]       * w_h_pw[j * 128 + t];
            s2 += w_fuse[o * 256 + 128 + j] * w_v_pw[j * 128 + t];
        }
        g_Wmain[o * 256 + t]       = __float2bfloat16(s1);
        g_Wmain[o * 256 + 128 + t] = __float2bfloat16(s2);
    } else if (o == 128) {
        for (int idx = t; idx < 32 * 128; idx += 128)
            g_Wdm1[idx] = __float2bfloat16(w_dm1[idx]);
    } else {
        for (int idx = t; idx < 128 * 32; idx += 128)
            g_Wdm2[idx] = __float2bfloat16(w_dm2[idx]);
    }
}

// ---- mma helpers ----
__device__ __forceinline__ void ldmatrix_x4(unsigned &r0, unsigned &r1, unsigned &r2, unsigned &r3,
                                            unsigned addr) {
    asm volatile("ldmatrix.sync.aligned.m8n8.x4.shared.b16 {%0,%1,%2,%3}, [%4];"
                 : "=r"(r0), "=r"(r1), "=r"(r2), "=r"(r3) : "r"(addr));
}
__device__ __forceinline__ void ldmatrix_x2t(unsigned &r0, unsigned &r1, unsigned addr) {
    asm volatile("ldmatrix.sync.aligned.m8n8.x2.trans.shared.b16 {%0,%1}, [%2];"
                 : "=r"(r0), "=r"(r1) : "r"(addr));
}
__device__ __forceinline__ void mma_bf16(float &c0, float &c1, float &c2, float &c3,
                                         unsigned a0, unsigned a1, unsigned a2, unsigned a3,
                                         unsigned b0, unsigned b1) {
    asm volatile("mma.sync.aligned.m16n8k16.row.col.f32.bf16.bf16.f32 "
                 "{%0,%1,%2,%3}, {%4,%5,%6,%7}, {%8,%9}, {%0,%1,%2,%3};"
                 : "+f"(c0), "+f"(c1), "+f"(c2), "+f"(c3)
                 : "r"(a0), "r"(a1), "r"(a2), "r"(a3), "r"(b0), "r"(b1));
}

// ---- shared memory layout (bytes) ----
// 0      : Wm     [128][WMP]   bf16  67584
// 67584  : act    [256][APITCH] bf16 61440   (aliased by d after main GEMM)
// 129024 : region 57344:
//            epi_s [128][APITCH] bf16 30720      | sx (f32 [128][104], 53248) during P1/P2
//            t_s   [32][APITCH]  bf16  7680
//            w1s   [32][W1P]     bf16  8704
//            w2s   [128][W2P]    bf16 10240
// 186368 : dwg    f32[1280]           5120
// total = 191488
#define SMEM_BYTES 191488

__global__ __launch_bounds__(256, 1)
void epi_mma_kernel(const float* __restrict__ x,
                    const float* __restrict__ w_h_dw,
                    const float* __restrict__ w_v_dw,
                    const float* __restrict__ scale_p,
                    float* __restrict__ out) {
    extern __shared__ char smem[];
    __nv_bfloat16* Wm    = (__nv_bfloat16*)(smem);
    __nv_bfloat16* act   = (__nv_bfloat16*)(smem + 67584);
    char* region = smem + 129024;
    __nv_bfloat16* epi_s = (__nv_bfloat16*)(region);
    __nv_bfloat16* t_s   = (__nv_bfloat16*)(region + 30720);
    __nv_bfloat16* w1s   = (__nv_bfloat16*)(region + 38400);
    __nv_bfloat16* w2s   = (__nv_bfloat16*)(region + 47104);
    float* sx  = (float*)(region);                 // [128][104] fp32, dead after P2
    float* dwg = (float*)(smem + 186368);
    __nv_bfloat16* d_s = act;                      // alias, written by dm2

    const int tid  = threadIdx.x;
    const int lane = tid & 31;
    const int warp = tid >> 5;
    const int C0 = blockIdx.x * 20;
    const int R0 = blockIdx.y * 5;
    const int b  = blockIdx.z;
    const float* xb = x + (long)b * Cdim * HW;

    // ---- P1: stage x tile + main weights + depthwise weights ----
    for (int idx = tid; idx < 3200; idx += 256) {
        int row = idx / 5, q = idx % 5;
        int c = row / 5, r = row % 5;
        float4 v = *(const float4*)(xb + (long)c * HW + (R0 + r) * 320 + C0 + q * 4);
        *(float4*)(sx + c * 104 + r * 20 + q * 4) = v;
    }
    for (int idx = tid; idx < 4096; idx += 256) {
        int row = idx >> 5, q = idx & 31;
        *(float4*)((char*)Wm + row * 528 + q * 16) = ((const float4*)g_Wmain)[idx];
    }
    for (int idx = tid; idx < 1280; idx += 256)
        dwg[idx] = (idx < 640) ? w_h_dw[idx] : w_v_dw[idx - 640];
    __syncthreads();

    // ---- P2: depthwise 1x5 / 5x1 within angular block + lrelu -> act (bf16, [K][N]) ----
    for (int idx = tid; idx < 12800; idx += 256) {
        int c = idx / 100, p = idx % 100;
        int r = p / 20, col = p % 20;
        int v = col % 5;
        const float* rowp = sx + c * 104 + r * 20;
        const float* wh = dwg + c * 5;
        const float* wv = dwg + 640 + c * 5;
        float hs = 0.f, vs = 0.f;
        #pragma unroll
        for (int k = 0; k < 5; ++k) {
            int d = k - 2;
            if (v + d >= 0 && v + d < 5) hs += wh[k] * rowp[col + d];
            if (r + d >= 0 && r + d < 5) vs += wv[k] * sx[c * 104 + (r + d) * 20 + col];
        }
        hs = hs > 0.f ? hs : 0.1f * hs;
        vs = vs > 0.f ? vs : 0.1f * vs;
        act[c * APITCH + p]           = __float2bfloat16(hs);
        act[(128 + c) * APITCH + p]   = __float2bfloat16(vs);
    }
    for (int idx = tid; idx < 5120; idx += 256) {      // zero pad cols 100..119
        int k = idx / 20, p = 100 + idx % 20;
        act[k * APITCH + p] = __float2bfloat16(0.f);
    }
    __syncthreads();

    // ---- copy dm weights into (now dead) sx region ----
    for (int idx = tid; idx < 512; idx += 256) {
        int row = idx >> 4, q = idx & 15;
        *(float4*)((char*)w1s + row * 272 + q * 16) = ((const float4*)g_Wdm1)[idx];
    }
    for (int idx = tid; idx < 512; idx += 256) {
        int row = idx >> 2, q = idx & 3;
        *(float4*)((char*)w2s + row * 80 + q * 16) = ((const float4*)g_Wdm2)[idx];
    }

    // ---- P3: main GEMM: epi[128][104] = Wm[128][256] @ act[256][104] ----
    const int o0 = warp * 16;
    float acc[13][4];
    #pragma unroll
    for (int nt = 0; nt < 13; ++nt)
        acc[nt][0] = acc[nt][1] = acc[nt][2] = acc[nt][3] = 0.f;

    unsigned aBase = (unsigned)__cvta_generic_to_shared(Wm)
                     + ((o0 + (lane & 15)) * WMP + (lane >> 4) * 8) * 2;
    unsigned bBase = (unsigned)__cvta_generic_to_shared(act)
                     + ((lane & 15) * APITCH) * 2;
    #pragma unroll
    for (int ks = 0; ks < 16; ++ks) {
        unsigned a0, a1, a2, a3;
        ldmatrix_x4(a0, a1, a2, a3, aBase + ks * 32);
        unsigned bRow = bBase + ks * 16 * APITCH * 2;
        #pragma unroll
        for (int nt = 0; nt < 13; ++nt) {
            unsigned b0, b1;
            ldmatrix_x2t(b0, b1, bRow + nt * 16);
            mma_bf16(acc[nt][0], acc[nt][1], acc[nt][2], acc[nt][3],
                     a0, a1, a2, a3, b0, b1);
        }
    }
    {
        int r = lane >> 2, cp = (lane & 3) * 2;
        #pragma unroll
        for (int nt = 0; nt < 13; ++nt) {
            int n = nt * 8 + cp;
            *(__nv_bfloat162*)(epi_s + (o0 + r) * APITCH + n)
                = __floats2bfloat162_rn(acc[nt][0], acc[nt][1]);
            *(__nv_bfloat162*)(epi_s + (o0 + r + 8) * APITCH + n)
                = __floats2bfloat162_rn(acc[nt][2], acc[nt][3]);
        }
    }
    __syncthreads();

    // ---- P4: dm1: t[32][104] = lrelu(Wdm1[32][128] @ epi[128][104]) ----
    {
        int g = warp >> 1, m0 = (warp & 1) * 16;
        float a1c[4][4];
        #pragma unroll
        for (int j = 0; j < 4; ++j)
            a1c[j][0] = a1c[j][1] = a1c[j][2] = a1c[j][3] = 0.f;
        unsigned aB = (unsigned)__cvta_generic_to_shared(w1s)
                      + ((m0 + (lane & 15)) * W1P + (lane >> 4) * 8) * 2;
        unsigned bB = (unsigned)__cvta_generic_to_shared(epi_s)
                      + ((lane & 15) * APITCH) * 2;
        #pragma unroll
        for (int ks = 0; ks < 8; ++ks) {
            unsigned a0, a1, a2, a3;
            ldmatrix_x4(a0, a1, a2, a3, aB + ks * 32);
            unsigned bRow = bB + ks * 16 * APITCH * 2;
            #pragma unroll
            for (int j = 0; j < 4; ++j) {
                int nt = g + j * 4;
                if (nt <= 12) {
                    unsigned b0, b1;
                    ldmatrix_x2t(b0, b1, bRow + nt * 16);
                    mma_bf16(a1c[j][0], a1c[j][1], a1c[j][2], a1c[j][3],
                             a0, a1, a2, a3, b0, b1);
                }
            }
        }
        int r = lane >> 2, cp = (lane & 3) * 2;
        #pragma unroll
        for (int j = 0; j < 4; ++j) {
            int nt = g + j * 4;
            if (nt <= 12) {
                int n = nt * 8 + cp;
                float v0 = a1c[j][0], v1 = a1c[j][1], v2 = a1c[j][2], v3 = a1c[j][3];
                v0 = v0 > 0.f ? v0 : 0.1f * v0;
                v1 = v1 > 0.f ? v1 : 0.1f * v1;
                v2 = v2 > 0.f ? v2 : 0.1f * v2;
                v3 = v3 > 0.f ? v3 : 0.1f * v3;
                *(__nv_bfloat162*)(t_s + (m0 + r) * APITCH + n)
                    = __floats2bfloat162_rn(v0, v1);
                *(__nv_bfloat162*)(t_s + (m0 + r + 8) * APITCH + n)
                    = __floats2bfloat162_rn(v2, v3);
            }
        }
    }
    __syncthreads();

    // ---- P5: dm2: d[128][104] = sigmoid(Wdm2[128][32] @ t[32][104]) ----
    {
        float a2c[13][4];
        #pragma unroll
        for (int nt = 0; nt < 13; ++nt)
            a2c[nt][0] = a2c[nt][1] = a2c[nt][2] = a2c[nt][3] = 0.f;
        unsigned aB = (unsigned)__cvta_generic_to_shared(w2s)
                      + ((o0 + (lane & 15)) * W2P + (lane >> 4) * 8) * 2;
        unsigned bB = (unsigned)__cvta_generic_to_shared(t_s)
                      + ((lane & 15) * APITCH) * 2;
        #pragma unroll
        for (int ks = 0; ks < 2; ++ks) {
            unsigned a0, a1, a2, a3;
            ldmatrix_x4(a0, a1, a2, a3, aB + ks * 32);
            unsigned bRow = bB + ks * 16 * APITCH * 2;
            #pragma unroll
            for (int nt = 0; nt < 13; ++nt) {
                unsigned b0, b1;
                ldmatrix_x2t(b0, b1, bRow + nt * 16);
                mma_bf16(a2c[nt][0], a2c[nt][1], a2c[nt][2], a2c[nt][3],
                         a0, a1, a2, a3, b0, b1);
            }
        }
        int r = lane >> 2, cp = (lane & 3) * 2;
        #pragma unroll
        for (int nt = 0; nt < 13; ++nt) {
            int n = nt * 8 + cp;
            float d0 = 1.f / (1.f + __expf(-a2c[nt][0]));
            float d1 = 1.f / (1.f + __expf(-a2c[nt][1]));
            float d2 = 1.f / (1.f + __expf(-a2c[nt][2]));
            float d3 = 1.f / (1.f + __expf(-a2c[nt][3]));
            *(__nv_bfloat162*)(d_s + (o0 + r) * APITCH + n)
                = __floats2bfloat162_rn(d0, d1);
            *(__nv_bfloat162*)(d_s + (o0 + r + 8) * APITCH + n)
                = __floats2bfloat162_rn(d2, d3);
        }
    }
    __syncthreads();

    // ---- P6: out = x + scale * epi * d (coalesced) ----
    const float s = scale_p[0];
    float* ob = out + (long)b * Cdim * HW;
    for (int idx = tid; idx < 12800; idx += 256) {
        int c = idx / 100, p = idx % 100;
        int r = p / 20, col = p % 20;
        long g = (long)c * HW + (long)(R0 + r) * 320 + C0 + col;
        float e = __bfloat162float(epi_s[c * APITCH + p]);
        float d = __bfloat162float(d_s[c * APITCH + p]);
        ob[g] = xb[g] + s * e * d;
    }
}

extern "C" void kernel_launch(void* const* d_in, const int* in_sizes, int n_in,
                              void* d_out, int out_size) {
    const float* x       = (const float*)d_in[0];
    const float* w_h_dw  = (const float*)d_in[1];
    const float* w_h_pw  = (const float*)d_in[2];
    const float* w_v_dw  = (const float*)d_in[3];
    const float* w_v_pw  = (const float*)d_in[4];
    const float* w_dm1   = (const float*)d_in[5];
    const float* w_dm2   = (const float*)d_in[6];
    const float* w_fuse  = (const float*)d_in[7];
    const float* scale   = (const float*)d_in[8];

    precompute_kernel<<<130, 128>>>(w_h_pw, w_v_pw, w_dm1, w_dm2, w_fuse);

    cudaFuncSetAttribute(epi_mma_kernel,
                         cudaFuncAttributeMaxDynamicSharedMemorySize, SMEM_BYTES);
    dim3 grid(320 / 20, 320 / 5, 2);
    epi_mma_kernel<<<grid, 256, SMEM_BYTES>>>(x, w_h_dw, w_v_dw, scale, (float*)d_out);
}

// round 3
// speedup vs baseline: 4.4748x; 2.3072x over previous
#include <cuda_runtime.h>
#include <cuda_bf16.h>

#define Cdim   128
#define HW     102400          // 320*320
#define APITCH 104             // act/epi/t pitch (elems): 208B rows, conflict-free ldmatrix.trans
#define WMP    264             // Wmain smem pitch
#define W1P    136             // Wdm1 smem pitch
#define W2P    40              // Wdm2 smem pitch

// ---- precomputed folded weights (bf16, device globals) ----
__device__ __align__(16) __nv_bfloat16 g_Wmain[128 * 256]; // [o][k]: k<128 Wch, k>=128 Wcv
__device__ __align__(16) __nv_bfloat16 g_Wdm1[32 * 128];   // [m][o]
__device__ __align__(16) __nv_bfloat16 g_Wdm2[128 * 32];   // [o][m]

__global__ void precompute_kernel(const float* __restrict__ w_h_pw,
                                  const float* __restrict__ w_v_pw,
                                  const float* __restrict__ w_dm1,
                                  const float* __restrict__ w_dm2,
                                  const float* __restrict__ w_fuse) {
    int o = blockIdx.x;
    int t = threadIdx.x;   // 128 threads
    if (o < 128) {
        float s1 = 0.f, s2 = 0.f;
        #pragma unroll 4
        for (int j = 0; j < 128; ++j) {
            s1 += w_fuse[o * 256 + j]       * w_h_pw[j * 128 + t];
            s2 += w_fuse[o * 256 + 128 + j] * w_v_pw[j * 128 + t];
        }
        g_Wmain[o * 256 + t]       = __float2bfloat16(s1);
        g_Wmain[o * 256 + 128 + t] = __float2bfloat16(s2);
    } else if (o == 128) {
        for (int idx = t; idx < 32 * 128; idx += 128)
            g_Wdm1[idx] = __float2bfloat16(w_dm1[idx]);
    } else {
        for (int idx = t; idx < 128 * 32; idx += 128)
            g_Wdm2[idx] = __float2bfloat16(w_dm2[idx]);
    }
}

// ---- mma helpers ----
__device__ __forceinline__ void ldmatrix_x4(unsigned &r0, unsigned &r1, unsigned &r2, unsigned &r3,
                                            unsigned addr) {
    asm volatile("ldmatrix.sync.aligned.m8n8.x4.shared.b16 {%0,%1,%2,%3}, [%4];"
                 : "=r"(r0), "=r"(r1), "=r"(r2), "=r"(r3) : "r"(addr));
}
__device__ __forceinline__ void ldmatrix_x2t(unsigned &r0, unsigned &r1, unsigned addr) {
    asm volatile("ldmatrix.sync.aligned.m8n8.x2.trans.shared.b16 {%0,%1}, [%2];"
                 : "=r"(r0), "=r"(r1) : "r"(addr));
}
__device__ __forceinline__ void mma_bf16(float &c0, float &c1, float &c2, float &c3,
                                         unsigned a0, unsigned a1, unsigned a2, unsigned a3,
                                         unsigned b0, unsigned b1) {
    asm volatile("mma.sync.aligned.m16n8k16.row.col.f32.bf16.bf16.f32 "
                 "{%0,%1,%2,%3}, {%4,%5,%6,%7}, {%8,%9}, {%0,%1,%2,%3};"
                 : "+f"(c0), "+f"(c1), "+f"(c2), "+f"(c3)
                 : "r"(a0), "r"(a1), "r"(a2), "r"(a3), "r"(b0), "r"(b1));
}

__device__ __forceinline__ float lrelu(float x) { return fmaxf(x, 0.1f * x); }

// 5-tap padded conv on 5 register values -> 5 outputs
__device__ __forceinline__ void conv5(const float w[5],
                                      float x0, float x1, float x2, float x3, float x4,
                                      float o[5]) {
    o[0] = w[2]*x0 + w[3]*x1 + w[4]*x2;
    o[1] = w[1]*x0 + w[2]*x1 + w[3]*x2 + w[4]*x3;
    o[2] = w[0]*x0 + w[1]*x1 + w[2]*x2 + w[3]*x3 + w[4]*x4;
    o[3] = w[0]*x1 + w[1]*x2 + w[2]*x3 + w[3]*x4;
    o[4] = w[0]*x2 + w[1]*x3 + w[2]*x4;
}

// ---- shared memory layout (bytes) ----
// 0      : Wm   [128][WMP]    bf16  67584
// 67584  : act  [256][APITCH] bf16  53248    (d_s aliases after main GEMM)
// 120832 : region (53248):
//            sx   f32 [128][104]    53248  (P1/P2 only)
//            epi_s [128][APITCH] bf16 26624  (+0)
//            t_s   [32][APITCH]  bf16  6656  (+26624)
//            w1s   [32][W1P]     bf16  8704  (+33280)
//            w2s   [128][W2P]    bf16 10240  (+41984)
// 174080 : dwg f32[1280]            5120
// total 179200
#define SMEM_BYTES 179200

__global__ __launch_bounds__(512, 1)
void epi_mma_kernel(const float* __restrict__ x,
                    const float* __restrict__ w_h_dw,
                    const float* __restrict__ w_v_dw,
                    const float* __restrict__ scale_p,
                    float* __restrict__ out) {
    extern __shared__ char smem[];
    __nv_bfloat16* Wm    = (__nv_bfloat16*)(smem);
    __nv_bfloat16* act   = (__nv_bfloat16*)(smem + 67584);
    char* region = smem + 120832;
    float* sx            = (float*)(region);
    __nv_bfloat16* epi_s = (__nv_bfloat16*)(region);
    __nv_bfloat16* t_s   = (__nv_bfloat16*)(region + 26624);
    __nv_bfloat16* w1s   = (__nv_bfloat16*)(region + 33280);
    __nv_bfloat16* w2s   = (__nv_bfloat16*)(region + 41984);
    float* dwg = (float*)(smem + 174080);
    __nv_bfloat16* d_s = act;   // alias; act dead after P3

    const int tid  = threadIdx.x;
    const int lane = tid & 31;
    const int warp = tid >> 5;
    const int C0 = blockIdx.x * 20;
    const int R0 = blockIdx.y * 5;
    const int b  = blockIdx.z;
    const float* xb = x + (long)b * Cdim * HW;

    // ---- P1: stage x tile + main weights + dw weights + zero act pad ----
    #pragma unroll
    for (int it = 0; it < 7; ++it) {             // 3200 float4 x-tile loads
        int idx = tid + it * 512;
        if (idx < 3200) {
            int row = idx / 5, q = idx - row * 5;
            int c = row / 5, r = row - c * 5;
            float4 v = *(const float4*)(xb + (long)c * HW + (R0 + r) * 320 + C0 + q * 4);
            *(float4*)(sx + c * 104 + r * 20 + q * 4) = v;
        }
    }
    #pragma unroll
    for (int it = 0; it < 8; ++it) {             // Wm: 4096 float4
        int idx = tid + it * 512;
        int row = idx >> 5, q = idx & 31;
        *(float4*)((char*)Wm + row * (WMP * 2) + q * 16) = ((const float4*)g_Wmain)[idx];
    }
    for (int idx = tid; idx < 1280; idx += 512)
        dwg[idx] = (idx < 640) ? w_h_dw[idx] : w_v_dw[idx - 640];
    {   // zero act cols 100..103 for all 256 rows
        int k = tid >> 1, q = tid & 1;
        *(__nv_bfloat162*)(act + k * APITCH + 100 + q * 2) = __floats2bfloat162_rn(0.f, 0.f);
    }
    __syncthreads();

    // ---- P2: depthwise 1x5 / 5x1 (block-local) + lrelu -> act bf16 [K][N] ----
    {
        const int c = tid >> 2, sub = tid & 3;
        float wh[5], wv[5];
        #pragma unroll
        for (int k = 0; k < 5; ++k) { wh[k] = dwg[c * 5 + k]; wv[k] = dwg[640 + c * 5 + k]; }
        const float* sxr = sx + c * 104;
        __nv_bfloat16* ah = act + c * APITCH;
        __nv_bfloat16* av = act + (128 + c) * APITCH;
        #pragma unroll
        for (int i = 0; i < 5; ++i) {
            {   // horizontal: row r=i, block blk=sub
                const float* p = sxr + i * 20 + sub * 5;
                float o[5];
                conv5(wh, p[0], p[1], p[2], p[3], p[4], o);
                __nv_bfloat16* q = ah + i * 20 + sub * 5;
                #pragma unroll
                for (int j = 0; j < 5; ++j) q[j] = __float2bfloat16(lrelu(o[j]));
            }
            {   // vertical: column col = sub + 4*i
                int col = sub + 4 * i;
                float o[5];
                conv5(wv, sxr[col], sxr[20 + col], sxr[40 + col], sxr[60 + col], sxr[80 + col], o);
                #pragma unroll
                for (int j = 0; j < 5; ++j) av[j * 20 + col] = __float2bfloat16(lrelu(o[j]));
            }
        }
    }
    __syncthreads();   // act ready; sx dead

    // ---- stage dm weights into region (sx dead now) ----
    {
        int idx = tid;
        if (idx < 512) {
            int row = idx >> 4, q = idx & 15;   // w1s: 32 rows x 16 float4
            *(float4*)((char*)w1s + row * (W1P * 2) + q * 16) = ((const float4*)g_Wdm1)[idx];
        }
    }
    {
        int row = tid >> 2, q = tid & 3;        // w2s: 128 rows x 4 float4
        *(float4*)((char*)w2s + row * (W2P * 2) + q * 16) = ((const float4*)g_Wdm2)[tid];
    }

    // ---- P3: main GEMM epi[128][104] = Wm[128][256] @ act[256][104] ----
    const int o0    = (warp & 7) * 16;
    const int nhalf = warp >> 3;
    const int nt0   = nhalf * 7;
    const int ncnt  = 7 - nhalf;          // 7 or 6 n-tiles
    float acc[7][4];
    #pragma unroll
    for (int j = 0; j < 7; ++j) acc[j][0] = acc[j][1] = acc[j][2] = acc[j][3] = 0.f;

    unsigned aBase = (unsigned)__cvta_generic_to_shared(Wm)
                     + ((o0 + (lane & 15)) * WMP + (lane >> 4) * 8) * 2;
    unsigned bBase = (unsigned)__cvta_generic_to_shared(act)
                     + ((lane & 15) * APITCH) * 2;
    #pragma unroll
    for (int ks = 0; ks < 16; ++ks) {
        unsigned a0, a1, a2, a3;
        ldmatrix_x4(a0, a1, a2, a3, aBase + ks * 32);
        unsigned bRow = bBase + ks * 16 * APITCH * 2 + nt0 * 16;
        #pragma unroll
        for (int j = 0; j < 7; ++j) {
            if (j < ncnt) {
                unsigned b0, b1;
                ldmatrix_x2t(b0, b1, bRow + j * 16);
                mma_bf16(acc[j][0], acc[j][1], acc[j][2], acc[j][3], a0, a1, a2, a3, b0, b1);
            }
        }
    }
    {
        int r = lane >> 2, cp = (lane & 3) * 2;
        #pragma unroll
        for (int j = 0; j < 7; ++j) {
            if (j < ncnt) {
                int n = (nt0 + j) * 8 + cp;
                *(__nv_bfloat162*)(epi_s + (o0 + r) * APITCH + n)
                    = __floats2bfloat162_rn(acc[j][0], acc[j][1]);
                *(__nv_bfloat162*)(epi_s + (o0 + r + 8) * APITCH + n)
                    = __floats2bfloat162_rn(acc[j][2], acc[j][3]);
            }
        }
    }
    __syncthreads();   // epi ready; w1s/w2s staged

    // ---- P4: dm1 t[32][104] = lrelu(Wdm1[32][128] @ epi) ----
    {
        int m0  = (warp & 1) * 16;
        int nt1 = warp >> 1;                 // 0..7
        int nt2 = nt1 + 8;                   // valid if warp < 10 (nt2 <= 12)
        bool has2 = (warp < 10);
        float c1[4] = {0.f, 0.f, 0.f, 0.f}, c2[4] = {0.f, 0.f, 0.f, 0.f};
        unsigned aB = (unsigned)__cvta_generic_to_shared(w1s)
                      + ((m0 + (lane & 15)) * W1P + (lane >> 4) * 8) * 2;
        unsigned bB = (unsigned)__cvta_generic_to_shared(epi_s)
                      + ((lane & 15) * APITCH) * 2;
        #pragma unroll
        for (int ks = 0; ks < 8; ++ks) {
            unsigned a0, a1, a2, a3;
            ldmatrix_x4(a0, a1, a2, a3, aB + ks * 32);
            unsigned bRow = bB + ks * 16 * APITCH * 2;
            unsigned b0, b1;
            ldmatrix_x2t(b0, b1, bRow + nt1 * 16);
            mma_bf16(c1[0], c1[1], c1[2], c1[3], a0, a1, a2, a3, b0, b1);
            if (has2) {
                ldmatrix_x2t(b0, b1, bRow + nt2 * 16);
                mma_bf16(c2[0], c2[1], c2[2], c2[3], a0, a1, a2, a3, b0, b1);
            }
        }
        int r = lane >> 2, cp = (lane & 3) * 2;
        {
            int n = nt1 * 8 + cp;
            *(__nv_bfloat162*)(t_s + (m0 + r) * APITCH + n)
                = __floats2bfloat162_rn(lrelu(c1[0]), lrelu(c1[1]));
            *(__nv_bfloat162*)(t_s + (m0 + r + 8) * APITCH + n)
                = __floats2bfloat162_rn(lrelu(c1[2]), lrelu(c1[3]));
        }
        if (has2) {
            int n = nt2 * 8 + cp;
            *(__nv_bfloat162*)(t_s + (m0 + r) * APITCH + n)
                = __floats2bfloat162_rn(lrelu(c2[0]), lrelu(c2[1]));
            *(__nv_bfloat162*)(t_s + (m0 + r + 8) * APITCH + n)
                = __floats2bfloat162_rn(lrelu(c2[2]), lrelu(c2[3]));
        }
    }
    __syncthreads();

    // ---- P5: dm2 d[128][104] = sigmoid(Wdm2[128][32] @ t) ----
    {
        float a2c[7][4];
        #pragma unroll
        for (int j = 0; j < 7; ++j) a2c[j][0] = a2c[j][1] = a2c[j][2] = a2c[j][3] = 0.f;
        unsigned aB = (unsigned)__cvta_generic_to_shared(w2s)
                      + ((o0 + (lane & 15)) * W2P + (lane >> 4) * 8) * 2;
        unsigned bB = (unsigned)__cvta_generic_to_shared(t_s)
                      + ((lane & 15) * APITCH) * 2;
        #pragma unroll
        for (int ks = 0; ks < 2; ++ks) {
            unsigned a0, a1, a2, a3;
            ldmatrix_x4(a0, a1, a2, a3, aB + ks * 32);
            unsigned bRow = bB + ks * 16 * APITCH * 2 + nt0 * 16;
            #pragma unroll
            for (int j = 0; j < 7; ++j) {
                if (j < ncnt) {
                    unsigned b0, b1;
                    ldmatrix_x2t(b0, b1, bRow + j * 16);
                    mma_bf16(a2c[j][0], a2c[j][1], a2c[j][2], a2c[j][3], a0, a1, a2, a3, b0, b1);
                }
            }
        }
        int r = lane >> 2, cp = (lane & 3) * 2;
        #pragma unroll
        for (int j = 0; j < 7; ++j) {
            if (j < ncnt) {
                int n = (nt0 + j) * 8 + cp;
                float d0 = 1.f / (1.f + __expf(-a2c[j][0]));
                float d1 = 1.f / (1.f + __expf(-a2c[j][1]));
                float d2 = 1.f / (1.f + __expf(-a2c[j][2]));
                float d3 = 1.f / (1.f + __expf(-a2c[j][3]));
                *(__nv_bfloat162*)(d_s + (o0 + r) * APITCH + n)
                    = __floats2bfloat162_rn(d0, d1);
                *(__nv_bfloat162*)(d_s + (o0 + r + 8) * APITCH + n)
                    = __floats2bfloat162_rn(d2, d3);
            }
        }
    }
    __syncthreads();

    // ---- P6: out = x + scale * epi * d (float4 / LDS.64) ----
    const float s = scale_p[0];
    float* ob = out + (long)b * Cdim * HW;
    #pragma unroll
    for (int it = 0; it < 7; ++it) {
        int idx = tid + it * 512;                  // 3200 vec4 tasks
        if (idx < 3200) {
            int c = idx / 25, rem = idx - c * 25;
            int r = rem / 5, v = rem - r * 5;
            long g = (long)c * HW + (long)(R0 + r) * 320 + C0 + v * 4;
            int pb = c * APITCH + r * 20 + v * 4;
            float4 xv = *(const float4*)(xb + g);
            __nv_bfloat162 ea = ((const __nv_bfloat162*)(epi_s + pb))[0];
            __nv_bfloat162 eb = ((const __nv_bfloat162*)(epi_s + pb))[1];
            __nv_bfloat162 da = ((const __nv_bfloat162*)(d_s + pb))[0];
            __nv_bfloat162 db = ((const __nv_bfloat162*)(d_s + pb))[1];
            float2 e0 = __bfloat1622float2(ea), e1 = __bfloat1622float2(eb);
            float2 f0 = __bfloat1622float2(da), f1 = __bfloat1622float2(db);
            xv.x += s * e0.x * f0.x;
            xv.y += s * e0.y * f0.y;
            xv.z += s * e1.x * f1.x;
            xv.w += s * e1.y * f1.y;
            *(float4*)(ob + g) = xv;
        }
    }
}

extern "C" void kernel_launch(void* const* d_in, const int* in_sizes, int n_in,
                              void* d_out, int out_size) {
    const float* x       = (const float*)d_in[0];
    const float* w_h_dw  = (const float*)d_in[1];
    const float* w_h_pw  = (const float*)d_in[2];
    const float* w_v_dw  = (const float*)d_in[3];
    const float* w_v_pw  = (const float*)d_in[4];
    const float* w_dm1   = (const float*)d_in[5];
    const float* w_dm2   = (const float*)d_in[6];
    const float* w_fuse  = (const float*)d_in[7];
    const float* scale   = (const float*)d_in[8];

    precompute_kernel<<<130, 128>>>(w_h_pw, w_v_pw, w_dm1, w_dm2, w_fuse);

    cudaFuncSetAttribute(epi_mma_kernel,
                         cudaFuncAttributeMaxDynamicSharedMemorySize, SMEM_BYTES);
    dim3 grid(320 / 20, 320 / 5, 2);
    epi_mma_kernel<<<grid, 512, SMEM_BYTES>>>(x, w_h_dw, w_v_dw, scale, (float*)d_out);
}

// round 4
// speedup vs baseline: 4.9548x; 1.1073x over previous
#include <cuda_runtime.h>
#include <cuda_bf16.h>

#define Cdim   128
#define HW     102400          // 320*320
#define APITCH 104             // act/epi/t pitch (elems): 208B rows, conflict-free ldmatrix.trans

// ---- precomputed folded weights ----
__device__ __align__(16) __nv_bfloat16 g_Wmain[128 * 256]; // [o][k] linear (staging for pack)
__device__ __align__(16) __nv_bfloat16 g_Wdm1[32 * 128];   // [m][o]
__device__ __align__(16) __nv_bfloat16 g_Wdm2[128 * 32];   // [o][m]
// fragment-order A operands: [tile][ks][lane][4 x u32]
__device__ __align__(16) unsigned g_WmainFrag[8 * 16 * 32 * 4];  // 64KB
__device__ __align__(16) unsigned g_Wdm1Frag[2 * 8 * 32 * 4];    // 8KB
__device__ __align__(16) unsigned g_Wdm2Frag[8 * 2 * 32 * 4];    // 2KB

__global__ void precompute_kernel(const float* __restrict__ w_h_pw,
                                  const float* __restrict__ w_v_pw,
                                  const float* __restrict__ w_dm1,
                                  const float* __restrict__ w_dm2,
                                  const float* __restrict__ w_fuse) {
    int o = blockIdx.x;
    int t = threadIdx.x;   // 128 threads
    if (o < 128) {
        float s1 = 0.f, s2 = 0.f;
        #pragma unroll 4
        for (int j = 0; j < 128; ++j) {
            s1 += w_fuse[o * 256 + j]       * w_h_pw[j * 128 + t];
            s2 += w_fuse[o * 256 + 128 + j] * w_v_pw[j * 128 + t];
        }
        g_Wmain[o * 256 + t]       = __float2bfloat16(s1);
        g_Wmain[o * 256 + 128 + t] = __float2bfloat16(s2);
    } else if (o == 128) {
        for (int idx = t; idx < 32 * 128; idx += 128)
            g_Wdm1[idx] = __float2bfloat16(w_dm1[idx]);
    } else {
        for (int idx = t; idx < 128 * 32; idx += 128)
            g_Wdm2[idx] = __float2bfloat16(w_dm2[idx]);
    }
}

__device__ __forceinline__ unsigned pack_bf2(__nv_bfloat16 lo, __nv_bfloat16 hi) {
    return ((unsigned)__bfloat16_as_ushort(hi) << 16) | __bfloat16_as_ushort(lo);
}

__global__ void pack_kernel() {
    int idx = blockIdx.x * blockDim.x + threadIdx.x;
    if (idx < 16384) {               // Wmain frags [8][16][32][4]
        int j = idx & 3, lane = (idx >> 2) & 31, ks = (idx >> 7) & 15, ot = idx >> 11;
        int row = ot * 16 + (lane >> 2) + (j & 1) * 8;
        int col = ks * 16 + (lane & 3) * 2 + (j >> 1) * 8;
        g_WmainFrag[idx] = pack_bf2(g_Wmain[row * 256 + col], g_Wmain[row * 256 + col + 1]);
    } else if (idx < 16384 + 2048) { // Wdm1 frags [2][8][32][4]
        int t = idx - 16384;
        int j = t & 3, lane = (t >> 2) & 31, ks = (t >> 7) & 7, mt = t >> 10;
        int row = mt * 16 + (lane >> 2) + (j & 1) * 8;
        int col = ks * 16 + (lane & 3) * 2 + (j >> 1) * 8;
        g_Wdm1Frag[t] = pack_bf2(g_Wdm1[row * 128 + col], g_Wdm1[row * 128 + col + 1]);
    } else if (idx < 16384 + 2048 + 512) { // Wdm2 frags [8][2][32][4]
        int t = idx - 16384 - 2048;
        int j = t & 3, lane = (t >> 2) & 31, ks = (t >> 7) & 1, ot = t >> 8;
        int row = ot * 16 + (lane >> 2) + (j & 1) * 8;
        int col = ks * 16 + (lane & 3) * 2 + (j >> 1) * 8;
        g_Wdm2Frag[t] = pack_bf2(g_Wdm2[row * 32 + col], g_Wdm2[row * 32 + col + 1]);
    }
}

// ---- mma helpers ----
__device__ __forceinline__ void ldmatrix_x2t(unsigned &r0, unsigned &r1, unsigned addr) {
    asm volatile("ldmatrix.sync.aligned.m8n8.x2.trans.shared.b16 {%0,%1}, [%2];"
                 : "=r"(r0), "=r"(r1) : "r"(addr));
}
__device__ __forceinline__ void mma_bf16(float &c0, float &c1, float &c2, float &c3,
                                         unsigned a0, unsigned a1, unsigned a2, unsigned a3,
                                         unsigned b0, unsigned b1) {
    asm volatile("mma.sync.aligned.m16n8k16.row.col.f32.bf16.bf16.f32 "
                 "{%0,%1,%2,%3}, {%4,%5,%6,%7}, {%8,%9}, {%0,%1,%2,%3};"
                 : "+f"(c0), "+f"(c1), "+f"(c2), "+f"(c3)
                 : "r"(a0), "r"(a1), "r"(a2), "r"(a3), "r"(b0), "r"(b1));
}

__device__ __forceinline__ float lrelu(float x) { return fmaxf(x, 0.1f * x); }

__device__ __forceinline__ void conv5(const float w[5],
                                      float x0, float x1, float x2, float x3, float x4,
                                      float o[5]) {
    o[0] = w[2]*x0 + w[3]*x1 + w[4]*x2;
    o[1] = w[1]*x0 + w[2]*x1 + w[3]*x2 + w[4]*x3;
    o[2] = w[0]*x0 + w[1]*x1 + w[2]*x2 + w[3]*x3 + w[4]*x4;
    o[3] = w[0]*x1 + w[1]*x2 + w[2]*x3 + w[3]*x4;
    o[4] = w[0]*x2 + w[1]*x3 + w[2]*x4;
}

// ---- shared memory layout (bytes) ----
// 0      : act [256][APITCH] bf16  53248   (d_s aliases after P3)
// 53248  : region (53248):
//            sx    f32 [128][104]      53248  (P1/P2 only)
//            epi_s [128][APITCH] bf16  26624  (+0)
//            t_s   [32][APITCH]  bf16   6656  (+26624)
// 106496 : dwg f32[1280]  5120
// total 111616  -> 2 CTAs/SM
#define SMEM_BYTES 111616

__global__ __launch_bounds__(512, 2)
void epi_mma_kernel(const float* __restrict__ x,
                    const float* __restrict__ w_h_dw,
                    const float* __restrict__ w_v_dw,
                    const float* __restrict__ scale_p,
                    float* __restrict__ out) {
    extern __shared__ char smem[];
    __nv_bfloat16* act   = (__nv_bfloat16*)(smem);
    char* region = smem + 53248;
    float* sx            = (float*)(region);
    __nv_bfloat16* epi_s = (__nv_bfloat16*)(region);
    __nv_bfloat16* t_s   = (__nv_bfloat16*)(region + 26624);
    float* dwg = (float*)(smem + 106496);
    __nv_bfloat16* d_s = act;   // alias; act dead after P3

    const int tid  = threadIdx.x;
    const int lane = tid & 31;
    const int warp = tid >> 5;
    const int C0 = blockIdx.x * 20;
    const int R0 = blockIdx.y * 5;
    const int b  = blockIdx.z;
    const float* xb = x + (long)b * Cdim * HW;

    // ---- P1: stage x tile + dw weights + zero act pad ----
    #pragma unroll
    for (int it = 0; it < 7; ++it) {
        int idx = tid + it * 512;
        if (idx < 3200) {
            int row = idx / 5, q = idx - row * 5;
            int c = row / 5, r = row - c * 5;
            float4 v = *(const float4*)(xb + (long)c * HW + (R0 + r) * 320 + C0 + q * 4);
            *(float4*)(sx + c * 104 + r * 20 + q * 4) = v;
        }
    }
    for (int idx = tid; idx < 1280; idx += 512)
        dwg[idx] = (idx < 640) ? w_h_dw[idx] : w_v_dw[idx - 640];
    {   // zero act cols 100..103 for all 256 rows
        int k = tid >> 1, q = tid & 1;
        *(__nv_bfloat162*)(act + k * APITCH + 100 + q * 2) = __floats2bfloat162_rn(0.f, 0.f);
    }
    __syncthreads();

    // ---- P2: depthwise 1x5 / 5x1 + lrelu -> act bf16 [K][N] ----
    {
        const int c = tid >> 2, sub = tid & 3;
        float wh[5], wv[5];
        #pragma unroll
        for (int k = 0; k < 5; ++k) { wh[k] = dwg[c * 5 + k]; wv[k] = dwg[640 + c * 5 + k]; }
        const float* sxr = sx + c * 104;
        __nv_bfloat16* ah = act + c * APITCH;
        __nv_bfloat16* av = act + (128 + c) * APITCH;
        #pragma unroll
        for (int i = 0; i < 5; ++i) {
            {   // horizontal: row i, angular block sub
                const float* p = sxr + i * 20 + sub * 5;
                float o[5];
                conv5(wh, p[0], p[1], p[2], p[3], p[4], o);
                __nv_bfloat16* q = ah + i * 20 + sub * 5;
                #pragma unroll
                for (int j = 0; j < 5; ++j) q[j] = __float2bfloat16(lrelu(o[j]));
            }
            {   // vertical: column sub + 4*i
                int col = sub + 4 * i;
                float o[5];
                conv5(wv, sxr[col], sxr[20 + col], sxr[40 + col], sxr[60 + col], sxr[80 + col], o);
                #pragma unroll
                for (int j = 0; j < 5; ++j) av[j * 20 + col] = __float2bfloat16(lrelu(o[j]));
            }
        }
    }
    __syncthreads();   // act ready; sx dead

    // ---- P3: main GEMM epi[128][104] = Wm[128][256] @ act[256][104] ----
    const int otile = warp & 7;
    const int o0    = otile * 16;
    const int nhalf = warp >> 3;
    const int nt0   = nhalf * 7;
    const int ncnt  = 7 - nhalf;
    float acc[7][4];
    #pragma unroll
    for (int j = 0; j < 7; ++j) acc[j][0] = acc[j][1] = acc[j][2] = acc[j][3] = 0.f;

    const uint4* wfA = ((const uint4*)g_WmainFrag) + otile * 16 * 32 + lane;
    unsigned bBase = (unsigned)__cvta_generic_to_shared(act)
                     + ((lane & 15) * APITCH + nt0 * 8) * 2;
    #pragma unroll
    for (int ks = 0; ks < 16; ++ks) {
        uint4 a = wfA[ks * 32];
        unsigned bRow = bBase + ks * 16 * APITCH * 2;
        #pragma unroll
        for (int j = 0; j < 7; ++j) {
            if (j < ncnt) {
                unsigned b0, b1;
                ldmatrix_x2t(b0, b1, bRow + j * 16);
                mma_bf16(acc[j][0], acc[j][1], acc[j][2], acc[j][3],
                         a.x, a.y, a.z, a.w, b0, b1);
            }
        }
    }
    {
        int r = lane >> 2, cp = (lane & 3) * 2;
        #pragma unroll
        for (int j = 0; j < 7; ++j) {
            if (j < ncnt) {
                int n = (nt0 + j) * 8 + cp;
                *(__nv_bfloat162*)(epi_s + (o0 + r) * APITCH + n)
                    = __floats2bfloat162_rn(acc[j][0], acc[j][1]);
                *(__nv_bfloat162*)(epi_s + (o0 + r + 8) * APITCH + n)
                    = __floats2bfloat162_rn(acc[j][2], acc[j][3]);
            }
        }
    }
    __syncthreads();   // epi ready (sx region now epi)

    // ---- P4: dm1 t[32][104] = lrelu(Wdm1[32][128] @ epi) ----
    {
        int mt = warp & 1, m0 = mt * 16;
        int nt1 = warp >> 1;
        int nt2 = nt1 + 8;
        bool has2 = (warp < 10);
        float c1[4] = {0.f, 0.f, 0.f, 0.f}, c2[4] = {0.f, 0.f, 0.f, 0.f};
        const uint4* wf1 = ((const uint4*)g_Wdm1Frag) + mt * 8 * 32 + lane;
        unsigned bB = (unsigned)__cvta_generic_to_shared(epi_s)
                      + ((lane & 15) * APITCH) * 2;
        #pragma unroll
        for (int ks = 0; ks < 8; ++ks) {
            uint4 a = wf1[ks * 32];
            unsigned bRow = bB + ks * 16 * APITCH * 2;
            unsigned b0, b1;
            ldmatrix_x2t(b0, b1, bRow + nt1 * 16);
            mma_bf16(c1[0], c1[1], c1[2], c1[3], a.x, a.y, a.z, a.w, b0, b1);
            if (has2) {
                ldmatrix_x2t(b0, b1, bRow + nt2 * 16);
                mma_bf16(c2[0], c2[1], c2[2], c2[3], a.x, a.y, a.z, a.w, b0, b1);
            }
        }
        int r = lane >> 2, cp = (lane & 3) * 2;
        {
            int n = nt1 * 8 + cp;
            *(__nv_bfloat162*)(t_s + (m0 + r) * APITCH + n)
                = __floats2bfloat162_rn(lrelu(c1[0]), lrelu(c1[1]));
            *(__nv_bfloat162*)(t_s + (m0 + r + 8) * APITCH + n)
                = __floats2bfloat162_rn(lrelu(c1[2]), lrelu(c1[3]));
        }
        if (has2) {
            int n = nt2 * 8 + cp;
            *(__nv_bfloat162*)(t_s + (m0 + r) * APITCH + n)
                = __floats2bfloat162_rn(lrelu(c2[0]), lrelu(c2[1]));
            *(__nv_bfloat162*)(t_s + (m0 + r + 8) * APITCH + n)
                = __floats2bfloat162_rn(lrelu(c2[2]), lrelu(c2[3]));
        }
    }
    __syncthreads();

    // ---- P5: dm2 d[128][104] = sigmoid(Wdm2[128][32] @ t) ----
    {
        float a2c[7][4];
        #pragma unroll
        for (int j = 0; j < 7; ++j) a2c[j][0] = a2c[j][1] = a2c[j][2] = a2c[j][3] = 0.f;
        const uint4* wf2 = ((const uint4*)g_Wdm2Frag) + otile * 2 * 32 + lane;
        unsigned bB = (unsigned)__cvta_generic_to_shared(t_s)
                      + ((lane & 15) * APITCH + nt0 * 8) * 2;
        #pragma unroll
        for (int ks = 0; ks < 2; ++ks) {
            uint4 a = wf2[ks * 32];
            unsigned bRow = bB + ks * 16 * APITCH * 2;
            #pragma unroll
            for (int j = 0; j < 7; ++j) {
                if (j < ncnt) {
                    unsigned b0, b1;
                    ldmatrix_x2t(b0, b1, bRow + j * 16);
                    mma_bf16(a2c[j][0], a2c[j][1], a2c[j][2], a2c[j][3],
                             a.x, a.y, a.z, a.w, b0, b1);
                }
            }
        }
        int r = lane >> 2, cp = (lane & 3) * 2;
        #pragma unroll
        for (int j = 0; j < 7; ++j) {
            if (j < ncnt) {
                int n = (nt0 + j) * 8 + cp;
                float d0 = 1.f / (1.f + __expf(-a2c[j][0]));
                float d1 = 1.f / (1.f + __expf(-a2c[j][1]));
                float d2 = 1.f / (1.f + __expf(-a2c[j][2]));
                float d3 = 1.f / (1.f + __expf(-a2c[j][3]));
                *(__nv_bfloat162*)(d_s + (o0 + r) * APITCH + n)
                    = __floats2bfloat162_rn(d0, d1);
                *(__nv_bfloat162*)(d_s + (o0 + r + 8) * APITCH + n)
                    = __floats2bfloat162_rn(d2, d3);
            }
        }
    }
    __syncthreads();

    // ---- P6: out = x + scale * epi * d (float4, x re-read from L2) ----
    const float s = scale_p[0];
    float* ob = out + (long)b * Cdim * HW;
    #pragma unroll
    for (int it = 0; it < 7; ++it) {
        int idx = tid + it * 512;
        if (idx < 3200) {
            int c = idx / 25, rem = idx - c * 25;
            int r = rem / 5, v = rem - r * 5;
            long g = (long)c * HW + (long)(R0 + r) * 320 + C0 + v * 4;
            int pb = c * APITCH + r * 20 + v * 4;
            float4 xv = *(const float4*)(xb + g);
            __nv_bfloat162 ea = ((const __nv_bfloat162*)(epi_s + pb))[0];
            __nv_bfloat162 eb = ((const __nv_bfloat162*)(epi_s + pb))[1];
            __nv_bfloat162 da = ((const __nv_bfloat162*)(d_s + pb))[0];
            __nv_bfloat162 db = ((const __nv_bfloat162*)(d_s + pb))[1];
            float2 e0 = __bfloat1622float2(ea), e1 = __bfloat1622float2(eb);
            float2 f0 = __bfloat1622float2(da), f1 = __bfloat1622float2(db);
            xv.x += s * e0.x * f0.x;
            xv.y += s * e0.y * f0.y;
            xv.z += s * e1.x * f1.x;
            xv.w += s * e1.y * f1.y;
            *(float4*)(ob + g) = xv;
        }
    }
}

extern "C" void kernel_launch(void* const* d_in, const int* in_sizes, int n_in,
                              void* d_out, int out_size) {
    const float* x       = (const float*)d_in[0];
    const float* w_h_dw  = (const float*)d_in[1];
    const float* w_h_pw  = (const float*)d_in[2];
    const float* w_v_dw  = (const float*)d_in[3];
    const float* w_v_pw  = (const float*)d_in[4];
    const float* w_dm1   = (const float*)d_in[5];
    const float* w_dm2   = (const float*)d_in[6];
    const float* w_fuse  = (const float*)d_in[7];
    const float* scale   = (const float*)d_in[8];

    precompute_kernel<<<130, 128>>>(w_h_pw, w_v_pw, w_dm1, w_dm2, w_fuse);
    pack_kernel<<<37, 512>>>();

    cudaFuncSetAttribute(epi_mma_kernel,
                         cudaFuncAttributeMaxDynamicSharedMemorySize, SMEM_BYTES);
    dim3 grid(320 / 20, 320 / 5, 2);
    epi_mma_kernel<<<grid, 512, SMEM_BYTES>>>(x, w_h_dw, w_v_dw, scale, (float*)d_out);
}